// round 12
// baseline (speedup 1.0000x reference)
#include <cuda_runtime.h>
#include <cuda_fp16.h>
#include <math.h>
#include <stdint.h>

// Problem dims (fixed per reference)
#define BATCH 8
#define SEQ   2048
#define DIM   512
#define MSEQ  (BATCH * SEQ)

#define BM 128
#define BN 128
#define NTHREADS 256

// 3-stage pipeline smem
#define HTILE 16384                   // one operand tile: 128 rows x 128B
#define STAGE_BYTES (2 * HTILE)
#define STAGES 3
#define HSMEM (STAGES * STAGE_BYTES)  // 96 KB

// Scratch (device globals; no runtime allocation allowed)
__device__ __half g_xh [(size_t)MSEQ * DIM];        // x in fp16
__device__ __half g_Wqh[(size_t)DIM * DIM];
__device__ __half g_Wkh[(size_t)DIM * DIM];
__device__ __half g_Wvh[(size_t)DIM * DIM];
__device__ __half g_Qh [(size_t)MSEQ * DIM];
__device__ __half g_Kh [(size_t)MSEQ * DIM];
__device__ __half g_VTh[(size_t)MSEQ * DIM];        // V transposed: [B][DIM][SEQ]
__device__ __half g_Sh [(size_t)BATCH * SEQ * SEQ]; // scores fp16, softmaxed in place

// ---------------------------------------------------------------------------
// asm helpers
// ---------------------------------------------------------------------------
__device__ __forceinline__ uint32_t smem_u32(const void* p) {
    uint32_t a;
    asm("{ .reg .u64 t; cvta.to.shared.u64 t, %1; cvt.u32.u64 %0, t; }" : "=r"(a) : "l"(p));
    return a;
}
#define LDSM4(r0, r1, r2, r3, addr) \
    asm volatile("ldmatrix.sync.aligned.m8n8.x4.shared.b16 {%0,%1,%2,%3}, [%4];" \
                 : "=r"(r0), "=r"(r1), "=r"(r2), "=r"(r3) : "r"(addr))
#define MMA16816(c, a, b0v, b1v) \
    asm volatile("mma.sync.aligned.m16n8k16.row.col.f32.f16.f16.f32 " \
                 "{%0,%1,%2,%3}, {%4,%5,%6,%7}, {%8,%9}, {%0,%1,%2,%3};" \
                 : "+f"((c)[0]), "+f"((c)[1]), "+f"((c)[2]), "+f"((c)[3]) \
                 : "r"((a)[0]), "r"((a)[1]), "r"((a)[2]), "r"((a)[3]), \
                   "r"(b0v), "r"(b1v))
#define CPASYNC16(dst, src) \
    asm volatile("cp.async.cg.shared.global [%0], [%1], 16;" :: "r"(dst), "l"(src))
#define CPCOMMIT() asm volatile("cp.async.commit_group;" ::: "memory")
#define CPWAIT1()  asm volatile("cp.async.wait_group 1;"  ::: "memory")

__device__ __forceinline__ uint32_t packh2(float a, float b) {
    __half2 h = __floats2half2_rn(a, b);
    return *(uint32_t*)&h;
}
__device__ __forceinline__ uint4 pack8(float4 a, float4 b) {
    uint4 u;
    u.x = packh2(a.x, a.y); u.y = packh2(a.z, a.w);
    u.z = packh2(b.x, b.y); u.w = packh2(b.z, b.w);
    return u;
}

// ===========================================================================
// One-shot f32 -> fp16 conversion of x, Wq, Wk, Wv (region-select by block)
// ===========================================================================
#define XBLK  (MSEQ * DIM / (256 * 8))   // 4096
#define WBLK  (DIM * DIM / (256 * 8))    // 128

__global__ __launch_bounds__(256)
void cvt_all(const float* __restrict__ x,  const float* __restrict__ Wq,
             const float* __restrict__ Wk, const float* __restrict__ Wv,
             __half* __restrict__ xh,  __half* __restrict__ Wqh,
             __half* __restrict__ Wkh, __half* __restrict__ Wvh)
{
    int blk = blockIdx.x;
    const float* in; __half* out;
    if (blk < XBLK)            { in = x;  out = xh; }
    else if (blk < XBLK + WBLK)     { blk -= XBLK;            in = Wq; out = Wqh; }
    else if (blk < XBLK + 2 * WBLK) { blk -= XBLK + WBLK;     in = Wk; out = Wkh; }
    else                            { blk -= XBLK + 2 * WBLK; in = Wv; out = Wvh; }
    const int i = (blk * 256 + threadIdx.x) * 8;
    float4 a = *(const float4*)(in + i);
    float4 b = *(const float4*)(in + i + 4);
    *(uint4*)(out + i) = pack8(a, b);
}

// ===========================================================================
// Shared GEMM mainloop (device inline): fills acc[4][4][4] for a 128x128 tile
// A,B fp16 K-major, cp.async 3-stage, SW128 swizzle. BK=64.
// ===========================================================================
struct GemmCtx {
    uint32_t sb0;
    int lrow, lc0, rx, arx;
    int wr, wc, lane_row, lane_ck;
};

__device__ __forceinline__ void gemm_main(const GemmCtx& c,
                                          const __half* __restrict__ Arow,
                                          const __half* __restrict__ Brow,
                                          int Ksz, float acc[4][4][4])
{
#pragma unroll
    for (int i = 0; i < 4; ++i)
#pragma unroll
        for (int j = 0; j < 4; ++j)
#pragma unroll
            for (int r = 0; r < 4; ++r) acc[i][j][r] = 0.0f;

    auto issue = [&](int k0, int s) {
        const uint32_t ab = c.sb0 + s * STAGE_BYTES + c.lrow * 128;
        const uint32_t bb = ab + HTILE;
#pragma unroll
        for (int j = 0; j < 4; ++j) {
            const int ck = c.lc0 + j;
            const uint32_t so = (uint32_t)((ck ^ c.rx) << 4);
            CPASYNC16(ab + so, Arow + k0 + ck * 8);
            CPASYNC16(bb + so, Brow + k0 + ck * 8);
        }
        CPCOMMIT();
    };

    const int niter = Ksz / 64;
    issue(0, 0);
    issue(64, 1);

    for (int it = 0; it < niter; ++it) {
        const int s = it % STAGES;
        CPWAIT1();
        __syncthreads();
        if (it + 2 < niter) issue((it + 2) * 64, (it + 2) % STAGES);
        else                CPCOMMIT();

        const uint32_t Ab32 = c.sb0 + s * STAGE_BYTES;
        const uint32_t Bb32 = Ab32 + HTILE;
#pragma unroll
        for (int kk = 0; kk < 4; ++kk) {
            const int ck = kk * 2 + c.lane_ck;
            uint32_t af[4][4];
            uint32_t bf[4][2];
#pragma unroll
            for (int fi = 0; fi < 4; ++fi) {
                const uint32_t addr = Ab32
                    + (c.wr * 64 + fi * 16 + c.lane_row) * 128
                    + ((ck ^ c.arx) << 4);
                LDSM4(af[fi][0], af[fi][1], af[fi][2], af[fi][3], addr);
            }
#pragma unroll
            for (int fjp = 0; fjp < 2; ++fjp) {
                uint32_t t0, t1, t2, t3;
                const uint32_t addr = Bb32
                    + (c.wc * 32 + fjp * 16 + c.lane_row) * 128
                    + ((ck ^ c.arx) << 4);
                LDSM4(t0, t1, t2, t3, addr);
                bf[fjp * 2][0]     = t0;  bf[fjp * 2][1]     = t2;
                bf[fjp * 2 + 1][0] = t1;  bf[fjp * 2 + 1][1] = t3;
            }
#pragma unroll
            for (int fi = 0; fi < 4; ++fi)
#pragma unroll
                for (int fj = 0; fj < 4; ++fj)
                    MMA16816(acc[fi][fj], af[fi], bf[fj][0], bf[fj][1]);
        }
    }
}

__device__ __forceinline__ GemmCtx make_ctx(uint32_t sb0) {
    GemmCtx c;
    const int tid  = threadIdx.x;
    const int lane = tid & 31;
    const int warp = tid >> 5;
    c.sb0 = sb0;
    c.lrow = tid & 127;
    c.lc0  = (tid >> 7) * 4;
    c.rx   = c.lrow & 7;
    c.wr   = warp >> 2;
    c.wc   = warp & 3;
    c.lane_row = lane & 15;
    c.lane_ck  = lane >> 4;
    c.arx = c.lane_row & 7;
    return c;
}

// ===========================================================================
// Attention GEMM: NT, OUT_MODE 0 = f32 row-major, 1 = fp16 row-major
// ===========================================================================
template <int OUT_MODE>
__global__ __launch_bounds__(NTHREADS, 2)
void gemm_attn(const __half* __restrict__ A, const __half* __restrict__ B,
               void* __restrict__ C,
               int lda, int ldb, int ldc, int Ksz,
               long long sA, long long sB, long long sC)
{
    extern __shared__ unsigned char hsm[];
    GemmCtx c = make_ctx(smem_u32(hsm));

    const int bm0 = blockIdx.y * BM;
    const int bn0 = blockIdx.x * BN;
    const long long z = blockIdx.z;
    const __half* Arow = A + z * sA + (long long)(bm0 + c.lrow) * lda;
    const __half* Brow = B + z * sB + (long long)(bn0 + c.lrow) * ldb;

    float acc[4][4][4];
    gemm_main(c, Arow, Brow, Ksz, acc);

    const int lane = threadIdx.x & 31;
    const int g = lane >> 2, tg = lane & 3;
#pragma unroll
    for (int fi = 0; fi < 4; ++fi) {
        const int r0 = bm0 + c.wr * 64 + fi * 16 + g;
        const int r1 = r0 + 8;
#pragma unroll
        for (int fj = 0; fj < 4; ++fj) {
            const int n = bn0 + c.wc * 32 + fj * 8 + 2 * tg;
            if (OUT_MODE == 0) {
                float* Cf = (float*)C + z * sC;
                *(float2*)(Cf + (long long)r0 * ldc + n) = make_float2(acc[fi][fj][0], acc[fi][fj][1]);
                *(float2*)(Cf + (long long)r1 * ldc + n) = make_float2(acc[fi][fj][2], acc[fi][fj][3]);
            } else {
                __half* Ch = (__half*)C + z * sC;
                *(__half2*)(Ch + (long long)r0 * ldc + n) = __floats2half2_rn(acc[fi][fj][0], acc[fi][fj][1]);
                *(__half2*)(Ch + (long long)r1 * ldc + n) = __floats2half2_rn(acc[fi][fj][2], acc[fi][fj][3]);
            }
        }
    }
}

// ===========================================================================
// Merged QKV projection: grid.z picks (W, bias, output, mode, scale)
//   z=0: Q = (x Wq^T + bq) * scale   -> fp16 row-major
//   z=1: K =  x Wk^T + bk            -> fp16 row-major
//   z=2: V =  x Wv^T + bv            -> fp16 transposed [B][DIM][SEQ]
// ===========================================================================
__global__ __launch_bounds__(NTHREADS, 2)
void gemm_qkv(const __half* __restrict__ xh,
              const __half* __restrict__ Wq, const __half* __restrict__ Wk,
              const __half* __restrict__ Wv,
              const float* __restrict__ bq, const float* __restrict__ bk,
              const float* __restrict__ bv,
              __half* __restrict__ Q, __half* __restrict__ K,
              __half* __restrict__ VT, float qscale)
{
    extern __shared__ unsigned char hsm[];
    GemmCtx c = make_ctx(smem_u32(hsm));

    const int zi = blockIdx.z;
    const __half* W    = (zi == 0) ? Wq : (zi == 1) ? Wk : Wv;
    const float*  bias = (zi == 0) ? bq : (zi == 1) ? bk : bv;
    const float   scale = (zi == 0) ? qscale : 1.0f;

    const int bm0 = blockIdx.y * BM;
    const int bn0 = blockIdx.x * BN;
    const __half* Arow = xh + (long long)(bm0 + c.lrow) * DIM;
    const __half* Brow = W  + (long long)(bn0 + c.lrow) * DIM;

    float acc[4][4][4];
    gemm_main(c, Arow, Brow, DIM, acc);

    const int lane = threadIdx.x & 31;
    const int g = lane >> 2, tg = lane & 3;
#pragma unroll
    for (int fi = 0; fi < 4; ++fi) {
        const int r0 = bm0 + c.wr * 64 + fi * 16 + g;
        const int r1 = r0 + 8;
#pragma unroll
        for (int fj = 0; fj < 4; ++fj) {
            const int n = bn0 + c.wc * 32 + fj * 8 + 2 * tg;
            const float b0v = bias[n], b1v = bias[n + 1];
            const float v00 = (acc[fi][fj][0] + b0v) * scale;
            const float v01 = (acc[fi][fj][1] + b1v) * scale;
            const float v10 = (acc[fi][fj][2] + b0v) * scale;
            const float v11 = (acc[fi][fj][3] + b1v) * scale;
            if (zi != 2) {
                __half* Ch = (zi == 0) ? Q : K;
                *(__half2*)(Ch + (long long)r0 * DIM + n) = __floats2half2_rn(v00, v01);
                *(__half2*)(Ch + (long long)r1 * DIM + n) = __floats2half2_rn(v10, v11);
            } else {
                const int b0i = r0 >> 11, s0 = r0 & (SEQ - 1);
                const int b1i = r1 >> 11, s1 = r1 & (SEQ - 1);
                __half* base0 = VT + (long long)b0i * DIM * SEQ + s0;
                __half* base1 = VT + (long long)b1i * DIM * SEQ + s1;
                base0[(long long)n * SEQ]       = __float2half_rn(v00);
                base0[(long long)(n + 1) * SEQ] = __float2half_rn(v01);
                base1[(long long)n * SEQ]       = __float2half_rn(v10);
                base1[(long long)(n + 1) * SEQ] = __float2half_rn(v11);
            }
        }
    }
}

// ===========================================================================
// Masked softmax, in place on fp16 scores. Scale folded into Q upstream.
// One block per row; block fully owns its row -> in-place is safe.
// ===========================================================================
__global__ __launch_bounds__(256)
void softmax_h(__half* __restrict__ S, const int* __restrict__ mask)
{
    const int row = blockIdx.x;
    const int b   = row >> 11;
    __half*    srow = S + (size_t)row * SEQ;
    const int* mrow = mask + b * SEQ;
    const int tid = threadIdx.x;
    const int base = tid * 8;

    uint4 sv = *(const uint4*)(srow + base);
    int4  m0 = *(const int4*)(mrow + base);
    int4  m1 = *(const int4*)(mrow + base + 4);

    __half2 h0 = *(__half2*)&sv.x, h1 = *(__half2*)&sv.y;
    __half2 h2 = *(__half2*)&sv.z, h3 = *(__half2*)&sv.w;

    float v[8];
    v[0] = m0.x ? __low2float(h0)  : -10000.0f;
    v[1] = m0.y ? __high2float(h0) : -10000.0f;
    v[2] = m0.z ? __low2float(h1)  : -10000.0f;
    v[3] = m0.w ? __high2float(h1) : -10000.0f;
    v[4] = m1.x ? __low2float(h2)  : -10000.0f;
    v[5] = m1.y ? __high2float(h2) : -10000.0f;
    v[6] = m1.z ? __low2float(h3)  : -10000.0f;
    v[7] = m1.w ? __high2float(h3) : -10000.0f;

    float mx = v[0];
#pragma unroll
    for (int i = 1; i < 8; ++i) mx = fmaxf(mx, v[i]);

    __shared__ float red[256];
    red[tid] = mx;
    __syncthreads();
#pragma unroll
    for (int s = 128; s > 0; s >>= 1) {
        if (tid < s) red[tid] = fmaxf(red[tid], red[tid + s]);
        __syncthreads();
    }
    mx = red[0];
    __syncthreads();

    float sum = 0.0f;
#pragma unroll
    for (int i = 0; i < 8; ++i) {
        v[i] = __expf(v[i] - mx);
        sum += v[i];
    }
    red[tid] = sum;
    __syncthreads();
#pragma unroll
    for (int s = 128; s > 0; s >>= 1) {
        if (tid < s) red[tid] += red[tid + s];
        __syncthreads();
    }
    const float inv = 1.0f / red[0];

    uint4 o;
    o.x = packh2(v[0] * inv, v[1] * inv);
    o.y = packh2(v[2] * inv, v[3] * inv);
    o.z = packh2(v[4] * inv, v[5] * inv);
    o.w = packh2(v[6] * inv, v[7] * inv);
    *(uint4*)(srow + base) = o;
}

// ---------------------------------------------------------------------------
// Launch. Inputs (metadata order): x, mask, Wq, bq, Wk, bk, Wv, bv
// ---------------------------------------------------------------------------
extern "C" void kernel_launch(void* const* d_in, const int* in_sizes, int n_in,
                              void* d_out, int out_size)
{
    (void)in_sizes; (void)n_in; (void)out_size;

    const float* x    = (const float*)d_in[0];
    const int*   mask = (const int*)  d_in[1];
    const float* Wq   = (const float*)d_in[2];
    const float* bq   = (const float*)d_in[3];
    const float* Wk   = (const float*)d_in[4];
    const float* bk   = (const float*)d_in[5];
    const float* Wv   = (const float*)d_in[6];
    const float* bv   = (const float*)d_in[7];
    float* out = (float*)d_out;

    __half *pxh, *pWq, *pWk, *pWv, *pQ, *pK, *pVT, *pS;
    cudaGetSymbolAddress((void**)&pxh, g_xh);
    cudaGetSymbolAddress((void**)&pWq, g_Wqh);
    cudaGetSymbolAddress((void**)&pWk, g_Wkh);
    cudaGetSymbolAddress((void**)&pWv, g_Wvh);
    cudaGetSymbolAddress((void**)&pQ,  g_Qh);
    cudaGetSymbolAddress((void**)&pK,  g_Kh);
    cudaGetSymbolAddress((void**)&pVT, g_VTh);
    cudaGetSymbolAddress((void**)&pS,  g_Sh);

    cudaFuncSetAttribute(gemm_attn<0>, cudaFuncAttributeMaxDynamicSharedMemorySize, HSMEM);
    cudaFuncSetAttribute(gemm_attn<1>, cudaFuncAttributeMaxDynamicSharedMemorySize, HSMEM);
    cudaFuncSetAttribute(gemm_qkv,     cudaFuncAttributeMaxDynamicSharedMemorySize, HSMEM);

    const float scale = 1.0f / sqrtf((float)DIM);

    // 0) convert x + weights to fp16 (one launch)
    cvt_all<<<XBLK + 3 * WBLK, 256>>>(x, Wq, Wk, Wv, pxh, pWq, pWk, pWv);

    // 1) QKV projections (one launch, grid.z = 3)
    {
        dim3 g(DIM / BN, MSEQ / BM, 3);   // (4, 128, 3)
        gemm_qkv<<<g, NTHREADS, HSMEM>>>(pxh, pWq, pWk, pWv, bq, bk, bv,
                                         pQ, pK, pVT, scale);
    }

    // 2) scores[b] = Qs[b] @ K[b]^T -> fp16 S
    {
        dim3 g(SEQ / BN, SEQ / BM, BATCH);   // (16, 16, 8)
        gemm_attn<1><<<g, NTHREADS, HSMEM>>>(pQ, pK, pS,
                                             DIM, DIM, SEQ, DIM,
                                             (long long)SEQ * DIM,
                                             (long long)SEQ * DIM,
                                             (long long)SEQ * SEQ);
    }

    // 3) masked softmax in place (fp16)
    softmax_h<<<BATCH * SEQ, 256>>>(pS, mask);

    // 4) out[b] = P[b] @ VT[b]^T -> f32
    {
        dim3 g(DIM / BN, SEQ / BM, BATCH);   // (4, 16, 8)
        gemm_attn<0><<<g, NTHREADS, HSMEM>>>(pS, pVT, out,
                                             SEQ, SEQ, DIM, SEQ,
                                             (long long)SEQ * SEQ,
                                             (long long)DIM * SEQ,
                                             (long long)SEQ * DIM);
    }
}

// round 16
// speedup vs baseline: 1.4895x; 1.4895x over previous
#include <cuda_runtime.h>
#include <cuda_fp16.h>
#include <math.h>
#include <stdint.h>

// Problem dims (fixed per reference)
#define BATCH 8
#define SEQ   2048
#define DIM   512
#define MSEQ  (BATCH * SEQ)

#define BM 128
#define BN 128
#define NTHREADS 256

// 3-stage pipeline smem
#define HTILE 16384                   // one operand tile: 128 rows x 128B
#define STAGE_BYTES (2 * HTILE)
#define STAGES 3
#define HSMEM (STAGES * STAGE_BYTES)  // 96 KB

// Scratch (device globals; no runtime allocation allowed)
__device__ __half g_xh [(size_t)MSEQ * DIM];        // x in fp16
__device__ __half g_Wqh[(size_t)DIM * DIM];
__device__ __half g_Wkh[(size_t)DIM * DIM];
__device__ __half g_Wvh[(size_t)DIM * DIM];
__device__ __half g_Qh [(size_t)MSEQ * DIM];
__device__ __half g_Kh [(size_t)MSEQ * DIM];
__device__ __half g_VTh[(size_t)MSEQ * DIM];        // V transposed: [B][DIM][SEQ]
__device__ __half g_Ph [(size_t)BATCH * SEQ * SEQ]; // softmax probs fp16
__device__ float  g_S  [(size_t)BATCH * SEQ * SEQ]; // raw scores f32

// ---------------------------------------------------------------------------
// asm helpers
// ---------------------------------------------------------------------------
__device__ __forceinline__ uint32_t smem_u32(const void* p) {
    uint32_t a;
    asm("{ .reg .u64 t; cvta.to.shared.u64 t, %1; cvt.u32.u64 %0, t; }" : "=r"(a) : "l"(p));
    return a;
}
#define LDSM4(r0, r1, r2, r3, addr) \
    asm volatile("ldmatrix.sync.aligned.m8n8.x4.shared.b16 {%0,%1,%2,%3}, [%4];" \
                 : "=r"(r0), "=r"(r1), "=r"(r2), "=r"(r3) : "r"(addr))
#define MMA16816(c, a, b0v, b1v) \
    asm volatile("mma.sync.aligned.m16n8k16.row.col.f32.f16.f16.f32 " \
                 "{%0,%1,%2,%3}, {%4,%5,%6,%7}, {%8,%9}, {%0,%1,%2,%3};" \
                 : "+f"((c)[0]), "+f"((c)[1]), "+f"((c)[2]), "+f"((c)[3]) \
                 : "r"((a)[0]), "r"((a)[1]), "r"((a)[2]), "r"((a)[3]), \
                   "r"(b0v), "r"(b1v))
#define CPASYNC16(dst, src) \
    asm volatile("cp.async.cg.shared.global [%0], [%1], 16;" :: "r"(dst), "l"(src))
#define CPCOMMIT() asm volatile("cp.async.commit_group;" ::: "memory")
#define CPWAIT1()  asm volatile("cp.async.wait_group 1;"  ::: "memory")

__device__ __forceinline__ uint32_t packh2(float a, float b) {
    __half2 h = __floats2half2_rn(a, b);
    return *(uint32_t*)&h;
}
__device__ __forceinline__ uint4 pack8(float4 a, float4 b) {
    uint4 u;
    u.x = packh2(a.x, a.y); u.y = packh2(a.z, a.w);
    u.z = packh2(b.x, b.y); u.w = packh2(b.z, b.w);
    return u;
}

// ===========================================================================
// One-shot f32 -> fp16 conversion of x, Wq, Wk, Wv (region-select by block)
// ===========================================================================
#define XBLK  (MSEQ * DIM / (256 * 8))   // 4096
#define WBLK  (DIM * DIM / (256 * 8))    // 128

__global__ __launch_bounds__(256)
void cvt_all(const float* __restrict__ x,  const float* __restrict__ Wq,
             const float* __restrict__ Wk, const float* __restrict__ Wv,
             __half* __restrict__ xh,  __half* __restrict__ Wqh,
             __half* __restrict__ Wkh, __half* __restrict__ Wvh)
{
    int blk = blockIdx.x;
    const float* in; __half* out;
    if (blk < XBLK)                 { in = x;  out = xh; }
    else if (blk < XBLK + WBLK)     { blk -= XBLK;            in = Wq; out = Wqh; }
    else if (blk < XBLK + 2 * WBLK) { blk -= XBLK + WBLK;     in = Wk; out = Wkh; }
    else                            { blk -= XBLK + 2 * WBLK; in = Wv; out = Wvh; }
    const int i = (blk * 256 + threadIdx.x) * 8;
    float4 a = *(const float4*)(in + i);
    float4 b = *(const float4*)(in + i + 4);
    *(uint4*)(out + i) = pack8(a, b);
}

// ===========================================================================
// Unified fp16 tensor-core NT GEMM, cp.async 3-stage, SW128 swizzle.
//   C[m,n] = (sum_k A[m,k]*B[n,k] + bias[n]) * scale
//   OUT_MODE: 0 = f32 row-major, 1 = fp16 row-major, 2 = fp16 transposed
//   BK = 64, 256 threads = 8 warps (2m x 4n), warp tile 64x32, 2 CTAs/SM.
// ===========================================================================
template <int OUT_MODE, bool ADD_BIAS>
__global__ __launch_bounds__(NTHREADS, 2)
void gemm_h16(const __half* __restrict__ A, const __half* __restrict__ B,
              const float* __restrict__ bias, void* __restrict__ C,
              int lda, int ldb, int ldc, int Ksz, float scale,
              long long sA, long long sB, long long sC)
{
    extern __shared__ unsigned char hsm[];
    const uint32_t sb0 = smem_u32(hsm);

    const int tid  = threadIdx.x;
    const int lane = tid & 31;
    const int warp = tid >> 5;
    const int g    = lane >> 2;
    const int tg   = lane & 3;
    const int wr   = warp >> 2;
    const int wc   = warp & 3;
    const int lane_row = lane & 15;
    const int lane_ck  = lane >> 4;

    const int bm0 = blockIdx.y * BM;
    const int bn0 = blockIdx.x * BN;
    const long long z = blockIdx.z;

    const int lrow = tid & 127;
    const int lc0  = (tid >> 7) * 4;
    const __half* Arow = A + z * sA + (long long)(bm0 + lrow) * lda;
    const __half* Brow = B + z * sB + (long long)(bn0 + lrow) * ldb;
    const int rx = lrow & 7;

    auto issue = [&](int k0, int s) {
        const uint32_t ab = sb0 + s * STAGE_BYTES + lrow * 128;
        const uint32_t bb = ab + HTILE;
#pragma unroll
        for (int j = 0; j < 4; ++j) {
            const int c = lc0 + j;
            const uint32_t so = (uint32_t)((c ^ rx) << 4);
            CPASYNC16(ab + so, Arow + k0 + c * 8);
            CPASYNC16(bb + so, Brow + k0 + c * 8);
        }
        CPCOMMIT();
    };

    float acc[4][4][4];
#pragma unroll
    for (int i = 0; i < 4; ++i)
#pragma unroll
        for (int j = 0; j < 4; ++j)
#pragma unroll
            for (int r = 0; r < 4; ++r) acc[i][j][r] = 0.0f;

    const int niter = Ksz / 64;
    issue(0, 0);
    issue(64, 1);

    const int arx = lane_row & 7;

    for (int it = 0; it < niter; ++it) {
        const int s = it % STAGES;
        CPWAIT1();
        __syncthreads();
        if (it + 2 < niter) issue((it + 2) * 64, (it + 2) % STAGES);
        else                CPCOMMIT();

        const uint32_t Ab32 = sb0 + s * STAGE_BYTES;
        const uint32_t Bb32 = Ab32 + HTILE;
#pragma unroll
        for (int kk = 0; kk < 4; ++kk) {
            const int ck = kk * 2 + lane_ck;
            uint32_t af[4][4];
            uint32_t bf[4][2];
#pragma unroll
            for (int fi = 0; fi < 4; ++fi) {
                const uint32_t addr = Ab32
                    + (wr * 64 + fi * 16 + lane_row) * 128
                    + ((ck ^ arx) << 4);
                LDSM4(af[fi][0], af[fi][1], af[fi][2], af[fi][3], addr);
            }
#pragma unroll
            for (int fjp = 0; fjp < 2; ++fjp) {
                uint32_t t0, t1, t2, t3;
                const uint32_t addr = Bb32
                    + (wc * 32 + fjp * 16 + lane_row) * 128
                    + ((ck ^ arx) << 4);
                LDSM4(t0, t1, t2, t3, addr);
                bf[fjp * 2][0]     = t0;  bf[fjp * 2][1]     = t2;
                bf[fjp * 2 + 1][0] = t1;  bf[fjp * 2 + 1][1] = t3;
            }
#pragma unroll
            for (int fi = 0; fi < 4; ++fi)
#pragma unroll
                for (int fj = 0; fj < 4; ++fj)
                    MMA16816(acc[fi][fj], af[fi], bf[fj][0], bf[fj][1]);
        }
    }

    // ---------------- Epilogue ----------------
#pragma unroll
    for (int fi = 0; fi < 4; ++fi) {
        const int r0 = bm0 + wr * 64 + fi * 16 + g;
        const int r1 = r0 + 8;
#pragma unroll
        for (int fj = 0; fj < 4; ++fj) {
            const int n = bn0 + wc * 32 + fj * 8 + 2 * tg;
            float b0v = 0.0f, b1v = 0.0f;
            if (ADD_BIAS) { b0v = bias[n]; b1v = bias[n + 1]; }
            const float v00 = (acc[fi][fj][0] + b0v) * scale;
            const float v01 = (acc[fi][fj][1] + b1v) * scale;
            const float v10 = (acc[fi][fj][2] + b0v) * scale;
            const float v11 = (acc[fi][fj][3] + b1v) * scale;

            if (OUT_MODE == 0) {
                float* Cf = (float*)C + z * sC;
                *(float2*)(Cf + (long long)r0 * ldc + n) = make_float2(v00, v01);
                *(float2*)(Cf + (long long)r1 * ldc + n) = make_float2(v10, v11);
            } else if (OUT_MODE == 1) {
                __half* Ch = (__half*)C + z * sC;
                *(__half2*)(Ch + (long long)r0 * ldc + n) = __floats2half2_rn(v00, v01);
                *(__half2*)(Ch + (long long)r1 * ldc + n) = __floats2half2_rn(v10, v11);
            } else {
                __half* Ch = (__half*)C;
                const int b0i = r0 >> 11, s0 = r0 & (SEQ - 1);
                const int b1i = r1 >> 11, s1 = r1 & (SEQ - 1);
                __half* base0 = Ch + (long long)b0i * DIM * SEQ + s0;
                __half* base1 = Ch + (long long)b1i * DIM * SEQ + s1;
                base0[(long long)n * SEQ]       = __float2half_rn(v00);
                base0[(long long)(n + 1) * SEQ] = __float2half_rn(v01);
                base1[(long long)n * SEQ]       = __float2half_rn(v10);
                base1[(long long)(n + 1) * SEQ] = __float2half_rn(v11);
            }
        }
    }
}

// ===========================================================================
// Masked softmax: S f32 in -> P fp16 out. Scale folded into Q upstream.
// Warp-shuffle reductions; 2 barriers total.
// ===========================================================================
__global__ __launch_bounds__(256)
void softmax_h(const float* __restrict__ S, __half* __restrict__ P,
               const int* __restrict__ mask)
{
    const int row = blockIdx.x;
    const int b   = row >> 11;
    const float* srow = S + (size_t)row * SEQ;
    __half*      prow = P + (size_t)row * SEQ;
    const int*   mrow = mask + b * SEQ;
    const int tid = threadIdx.x;
    const int lane = tid & 31;
    const int warp = tid >> 5;
    const int base = tid * 8;

    float4 s0 = *(const float4*)(srow + base);
    float4 s1 = *(const float4*)(srow + base + 4);
    int4   m0 = *(const int4*)(mrow + base);
    int4   m1 = *(const int4*)(mrow + base + 4);

    float v[8];
    v[0] = m0.x ? s0.x : -10000.0f;
    v[1] = m0.y ? s0.y : -10000.0f;
    v[2] = m0.z ? s0.z : -10000.0f;
    v[3] = m0.w ? s0.w : -10000.0f;
    v[4] = m1.x ? s1.x : -10000.0f;
    v[5] = m1.y ? s1.y : -10000.0f;
    v[6] = m1.z ? s1.z : -10000.0f;
    v[7] = m1.w ? s1.w : -10000.0f;

    float mx = v[0];
#pragma unroll
    for (int i = 1; i < 8; ++i) mx = fmaxf(mx, v[i]);
#pragma unroll
    for (int d = 16; d > 0; d >>= 1)
        mx = fmaxf(mx, __shfl_xor_sync(0xFFFFFFFFu, mx, d));

    __shared__ float redm[8], reds[8];
    if (lane == 0) redm[warp] = mx;
    __syncthreads();
    {
        float t = redm[lane & 7];
#pragma unroll
        for (int d = 4; d > 0; d >>= 1)
            t = fmaxf(t, __shfl_xor_sync(0xFFFFFFFFu, t, d));
        mx = t;
    }

    float sum = 0.0f;
#pragma unroll
    for (int i = 0; i < 8; ++i) {
        v[i] = __expf(v[i] - mx);
        sum += v[i];
    }
#pragma unroll
    for (int d = 16; d > 0; d >>= 1)
        sum += __shfl_xor_sync(0xFFFFFFFFu, sum, d);
    if (lane == 0) reds[warp] = sum;
    __syncthreads();
    {
        float t = reds[lane & 7];
#pragma unroll
        for (int d = 4; d > 0; d >>= 1)
            t += __shfl_xor_sync(0xFFFFFFFFu, t, d);
        sum = t;
    }
    const float inv = 1.0f / sum;

    uint4 o;
    o.x = packh2(v[0] * inv, v[1] * inv);
    o.y = packh2(v[2] * inv, v[3] * inv);
    o.z = packh2(v[4] * inv, v[5] * inv);
    o.w = packh2(v[6] * inv, v[7] * inv);
    *(uint4*)(prow + base) = o;
}

// ---------------------------------------------------------------------------
// Launch. Inputs (metadata order): x, mask, Wq, bq, Wk, bk, Wv, bv
// ---------------------------------------------------------------------------
extern "C" void kernel_launch(void* const* d_in, const int* in_sizes, int n_in,
                              void* d_out, int out_size)
{
    (void)in_sizes; (void)n_in; (void)out_size;

    const float* x    = (const float*)d_in[0];
    const int*   mask = (const int*)  d_in[1];
    const float* Wq   = (const float*)d_in[2];
    const float* bq   = (const float*)d_in[3];
    const float* Wk   = (const float*)d_in[4];
    const float* bk   = (const float*)d_in[5];
    const float* Wv   = (const float*)d_in[6];
    const float* bv   = (const float*)d_in[7];
    float* out = (float*)d_out;

    __half *pxh, *pWq, *pWk, *pWv, *pQ, *pK, *pVT, *pP;
    float  *pS;
    cudaGetSymbolAddress((void**)&pxh, g_xh);
    cudaGetSymbolAddress((void**)&pWq, g_Wqh);
    cudaGetSymbolAddress((void**)&pWk, g_Wkh);
    cudaGetSymbolAddress((void**)&pWv, g_Wvh);
    cudaGetSymbolAddress((void**)&pQ,  g_Qh);
    cudaGetSymbolAddress((void**)&pK,  g_Kh);
    cudaGetSymbolAddress((void**)&pVT, g_VTh);
    cudaGetSymbolAddress((void**)&pP,  g_Ph);
    cudaGetSymbolAddress((void**)&pS,  g_S);

    cudaFuncSetAttribute(gemm_h16<0, false>, cudaFuncAttributeMaxDynamicSharedMemorySize, HSMEM);
    cudaFuncSetAttribute(gemm_h16<1, true >, cudaFuncAttributeMaxDynamicSharedMemorySize, HSMEM);
    cudaFuncSetAttribute(gemm_h16<2, true >, cudaFuncAttributeMaxDynamicSharedMemorySize, HSMEM);

    const float scale = 1.0f / sqrtf((float)DIM);

    // 0) convert x and weights to fp16 (one launch)
    cvt_all<<<XBLK + 3 * WBLK, 256>>>(x, Wq, Wk, Wv, pxh, pWq, pWk, pWv);

    // 1) QKV projections (fp16 in/out); scale folded into Q; V written transposed
    {
        dim3 g(DIM / BN, MSEQ / BM, 1);   // (4, 128, 1)
        gemm_h16<1, true><<<g, NTHREADS, HSMEM>>>(pxh, pWq, bq, pQ,  DIM, DIM, DIM, DIM, scale, 0, 0, 0);
        gemm_h16<1, true><<<g, NTHREADS, HSMEM>>>(pxh, pWk, bk, pK,  DIM, DIM, DIM, DIM, 1.0f,  0, 0, 0);
        gemm_h16<2, true><<<g, NTHREADS, HSMEM>>>(pxh, pWv, bv, pVT, DIM, DIM, 0,   DIM, 1.0f,  0, 0, 0);
    }

    // 2) scores[b] = Qs[b] @ K[b]^T  -> f32 S
    {
        dim3 g(SEQ / BN, SEQ / BM, BATCH);   // (16, 16, 8)
        gemm_h16<0, false><<<g, NTHREADS, HSMEM>>>(pQ, pK, nullptr, pS,
                                                   DIM, DIM, SEQ, DIM, 1.0f,
                                                   (long long)SEQ * DIM,
                                                   (long long)SEQ * DIM,
                                                   (long long)SEQ * SEQ);
    }

    // 3) masked softmax: S f32 -> P fp16
    softmax_h<<<BATCH * SEQ, 256>>>(pS, pP, mask);

    // 4) out[b] = P[b] @ VT[b]^T  (NT: VT is [DIM][SEQ] K-major), f32 out
    {
        dim3 g(DIM / BN, SEQ / BM, BATCH);   // (4, 16, 8)
        gemm_h16<0, false><<<g, NTHREADS, HSMEM>>>(pP, pVT, nullptr, out,
                                                   SEQ, SEQ, DIM, SEQ, 1.0f,
                                                   (long long)SEQ * SEQ,
                                                   (long long)DIM * SEQ,
                                                   (long long)SEQ * DIM);
    }
}